// round 8
// baseline (speedup 1.0000x reference)
#include <cuda_runtime.h>
#include <cstdint>

// Math after collapse (verified, rel_err ~9e-7):
//   attn == 1/H exactly (softmax over an exactly-broadcast head axis)
//   sv[b,j]  = <sum_q v[b,q,:], Wv[j,:]> + Sq*bv[j]
//   row[b,d] = (1/H) * <sv[b,:], Wb[d,:]> + bb[d]
//   out[s,b,d] = row[b,d]  for all s
// Linearity: sv[b,j] = sum over phase-1 blocks x (with x%4==b) of
//   <partial_x, Wv[j,:]>  — so each block projects its own partial, and the
//   512 KB g_partial round-trip + one grid sync disappear.
static constexpr int B  = 4;
static constexpr int SQ = 1024;
static constexpr int SK = 1024;
static constexpr int D  = 1024;
static constexpr int DH = 64;
static constexpr int H  = 16;

static constexpr int QS = 32;             // q-splits
static constexpr int NB = B * QS;         // 128 blocks — single co-resident wave
static constexpr int P2 = 32;             // phase-2 blocks: (b, c), c = 128-d chunk

static constexpr int ROW_F4   = B * D / 4;              // 1024 float4 = 16 KB tile
static constexpr int BLK_F4   = (SK * B * D / 4) / NB;  // 8192 float4 per block
static constexpr int TILES_PB = BLK_F4 / ROW_F4;        // 8

// Scratch (__device__ globals; no allocation allowed)
__device__ float g_svp2[NB * DH];         // 32 KB: per-block projected partials
__device__ float g_row[B * D];            // 16 KB
__device__ unsigned long long g_tick[2];  // monotonic ticket counters (never reset)

__device__ __forceinline__ float4 ldcs4(const float4* p) {   // streaming read
    float4 r;
    asm volatile("ld.global.cs.v4.f32 {%0,%1,%2,%3}, [%4];"
                 : "=f"(r.x), "=f"(r.y), "=f"(r.z), "=f"(r.w) : "l"(p));
    return r;
}
__device__ __forceinline__ float4 ldcg4(const float4* p) {   // L2-coherent read
    float4 r;
    asm volatile("ld.global.cg.v4.f32 {%0,%1,%2,%3}, [%4];"
                 : "=f"(r.x), "=f"(r.y), "=f"(r.z), "=f"(r.w) : "l"(p));
    return r;
}
__device__ __forceinline__ float ldcg1(const float* p) {
    float r;
    asm volatile("ld.global.cg.f32 %0, [%1];" : "=f"(r) : "l"(p));
    return r;
}
__device__ __forceinline__ void stcs4(float4* p, float4 v) { // streaming store
    asm volatile("st.global.cs.v4.f32 [%0], {%1,%2,%3,%4};"
                 :: "l"(p), "f"(v.x), "f"(v.y), "f"(v.z), "f"(v.w) : "memory");
}
__device__ __forceinline__ unsigned long long ld_acq(const unsigned long long* p) {
    unsigned long long v;
    asm volatile("ld.global.acquire.gpu.u64 %0, [%1];" : "=l"(v) : "l"(p));
    return v;
}
// Arrive: caller must __syncthreads() first. Thread 0: release + bump.
__device__ __forceinline__ unsigned long long arrive(int i) {
    __threadfence();
    return atomicAdd(&g_tick[i], 1ULL);
}
__device__ __forceinline__ void wait_for(int i, unsigned long long target) {
    if (threadIdx.x == 0)
        while (ld_acq(&g_tick[i]) < target) __nanosleep(64);
    __syncthreads();
}

// ---------------------------------------------------------------------------
// One persistent kernel, 128 blocks x 1024 threads (co-resident wave).
//  phase 1 (128 blocks): partial v-column-sum (smem) + in-block Wv projection
//                        -> g_svp2[x][64]           ... arrive(0)
//  phase 2 ( 32 blocks): sv[b] = sum_x svp2 + Sq*bv; row-slice via Wb
//                        -> g_row                   ... arrive(1)
//  phase 3 (128 blocks): broadcast-store 16 MB (streaming stores)
// Replay-safe monotonic tickets (launches serialize; counters only grow).
// ---------------------------------------------------------------------------
__global__ void __launch_bounds__(1024)
fused_kernel(const float* __restrict__ v,
             const float* __restrict__ Wv, const float* __restrict__ bv,
             const float* __restrict__ Wb, const float* __restrict__ bb,
             float4* __restrict__ out4) {
    __shared__ float4 sred[1024];     // 16 KB strip-reduce buffer
    __shared__ float  s_v[D];         // 4 KB: this block's partial vsum
    __shared__ float  s_sv[DH];
    __shared__ unsigned long long s_round;

    const int x = blockIdx.x;
    const int t = threadIdx.x;

    // ---------------- phase 1: partial column-sum + Wv projection ----------
    {
        const int b  = x & 3;
        const int qs = x >> 2;
        const int t4    = t & 255;    // float4 slot in D
        const int strip = t >> 8;     // 0..3
        const float4* vb = reinterpret_cast<const float4*>(v + (size_t)b * SQ * D);
        const int q0 = qs * 32 + strip * 8;

        float4 acc = make_float4(0.f, 0.f, 0.f, 0.f);
#pragma unroll
        for (int r = 0; r < 8; ++r) {
            float4 xv = ldcs4(&vb[(size_t)(q0 + r) * (D / 4) + t4]);
            acc.x += xv.x; acc.y += xv.y; acc.z += xv.z; acc.w += xv.w;
        }
        sred[strip * 256 + t4] = acc;
        __syncthreads();
        if (strip == 0) {
            float4 a0 = sred[t4], a1 = sred[256 + t4], a2 = sred[512 + t4], a3 = sred[768 + t4];
            float4 s;
            s.x = (a0.x + a1.x) + (a2.x + a3.x);
            s.y = (a0.y + a1.y) + (a2.y + a3.y);
            s.z = (a0.z + a1.z) + (a2.z + a3.z);
            s.w = (a0.w + a1.w) + (a2.w + a3.w);
            reinterpret_cast<float4*>(s_v)[t4] = s;
        }
        __syncthreads();

        // project: svp2[x][j] = <s_v, Wv[j,:]> ; 32 warps x 2 j's each
        const int warp = t >> 5, lane = t & 31;
        const float4* sv4 = reinterpret_cast<const float4*>(s_v);
#pragma unroll
        for (int jj = 0; jj < 2; ++jj) {
            const int j = warp * 2 + jj;
            const float4* wr = reinterpret_cast<const float4*>(Wv + (size_t)j * D);
            float s = 0.f;
#pragma unroll
            for (int i = 0; i < 8; ++i) {
                float4 w = __ldg(&wr[lane + i * 32]);
                float4 a = sv4[lane + i * 32];
                s += a.x * w.x + a.y * w.y + a.z * w.z + a.w * w.w;
            }
#pragma unroll
            for (int o = 16; o > 0; o >>= 1) s += __shfl_xor_sync(0xFFFFFFFFu, s, o);
            if (lane == 0) g_svp2[x * DH + j] = s;
        }
    }

    __syncthreads();
    if (t == 0) s_round = arrive(0) / NB;
    __syncthreads();
    const unsigned long long round = s_round;

    // ---------------- phase 2 (blocks 0..31): sv + row slice ---------------
    if (x < P2) {
        const int b = x & 3;
        const int c = x >> 2;                 // d-chunk of 128

        wait_for(0, (round + 1) * NB);        // all svp2 visible

        if (t < DH) {
            float s = (float)SQ * __ldg(&bv[t]);
#pragma unroll
            for (int qs = 0; qs < QS; ++qs)
                s += ldcg1(&g_svp2[(qs * B + b) * DH + t]);
            s_sv[t] = s;
        }
        __syncthreads();

        if (t < 128) {
            const int d = c * 128 + t;
            const float4* wb = reinterpret_cast<const float4*>(Wb + (size_t)d * DH);
            float s = 0.f;
#pragma unroll
            for (int j4 = 0; j4 < DH / 4; ++j4) {
                float4 w = __ldg(&wb[j4]);
                s += s_sv[j4 * 4 + 0] * w.x + s_sv[j4 * 4 + 1] * w.y
                   + s_sv[j4 * 4 + 2] * w.z + s_sv[j4 * 4 + 3] * w.w;
            }
            g_row[b * D + d] = s * (1.0f / (float)H) + __ldg(&bb[d]);
        }
        __syncthreads();
        if (t == 0) arrive(1);
    }

    // ---------------- phase 3: broadcast-store 16 MB -----------------------
    wait_for(1, (round + 1) * P2);            // g_row complete

    {
        const float4 val = ldcg4(&reinterpret_cast<const float4*>(g_row)[t]);
        float4* o = out4 + (size_t)x * BLK_F4;
#pragma unroll
        for (int r = 0; r < TILES_PB; ++r)
            stcs4(&o[r * ROW_F4 + t], val);
    }
}

extern "C" void kernel_launch(void* const* d_in, const int* in_sizes, int n_in,
                              void* d_out, int out_size) {
    // Inputs: 0=q 1=k 2=h 3=w 4=v 5=Wq 6=bq 7=Wk 8=bk 9=Wv 10=bv 11=Wb 12=bb
    const float* v  = (const float*)d_in[4];
    const float* Wv = (const float*)d_in[9];
    const float* bv = (const float*)d_in[10];
    const float* Wb = (const float*)d_in[11];
    const float* bb = (const float*)d_in[12];

    fused_kernel<<<NB, 1024>>>(v, Wv, bv, Wb, bb, (float4*)d_out);
}

// round 10
// speedup vs baseline: 1.1496x; 1.1496x over previous
#include <cuda_runtime.h>
#include <cstdint>

// Math after collapse (verified, rel_err ~9e-7):
//   attn == 1/H exactly (softmax over an exactly-broadcast head axis)
//   sv[b,j]  = <sum_q v[b,q,:], Wv[j,:]> + Sq*bv[j]
//   row[b,d] = (1/H) * <sv[b,:], Wb[d,:]> + bb[d]
//   out[s,b,d] = row[b,d]  for all s
// Linearity: sv[b,j] = sum over phase-1 blocks x (x%4==b) of <partial_x, Wv[j,:]>.
static constexpr int B  = 4;
static constexpr int SQ = 1024;
static constexpr int SK = 1024;
static constexpr int D  = 1024;
static constexpr int DH = 64;
static constexpr int H  = 16;

static constexpr int QS = 32;             // q-splits
static constexpr int NB = B * QS;         // 128 blocks — single co-resident wave

static constexpr int ROW_F4 = B * D / 4;  // 1024 float4 per output tile (16 KB)
// Slice decomposition of the row tile: 32 slices x 128 floats (512 B each).
// Block x owns slice s = x & 31 and tile-group g = x >> 5 (256 tiles each).

// Scratch (__device__ globals; no allocation allowed)
__device__ float g_svp2[NB * DH];         // 32 KB: per-block projected partials
__device__ unsigned long long g_tick;     // monotonic ticket counter (never reset)

__device__ __forceinline__ float ldcg1(const float* p) {
    float r;
    asm volatile("ld.global.cg.f32 %0, [%1];" : "=f"(r) : "l"(p));
    return r;
}
__device__ __forceinline__ unsigned long long ld_acq(const unsigned long long* p) {
    unsigned long long v;
    asm volatile("ld.global.acquire.gpu.u64 %0, [%1];" : "=l"(v) : "l"(p));
    return v;
}

// ---------------------------------------------------------------------------
// One persistent kernel, 128 blocks x 1024 threads (co-resident wave).
//  phase 1 (all blocks): partial v-column-sum (smem) + in-block Wv projection
//                        -> g_svp2[x][64]
//  single replay-safe grid sync (monotonic ticket counter)
//  phase 2 (all blocks, independent): sv[b] from svp2; 128-float row slice
//                        via Wb slice; store slice into 256 tiles.
// ---------------------------------------------------------------------------
__global__ void __launch_bounds__(1024)
fused_kernel(const float* __restrict__ v,
             const float* __restrict__ Wv, const float* __restrict__ bv,
             const float* __restrict__ Wb, const float* __restrict__ bb,
             float4* __restrict__ out4) {
    __shared__ float4 sred[1024];     // 16 KB strip-reduce buffer
    __shared__ float  s_v[D];         // 4 KB: this block's partial vsum
    __shared__ float  s_sv[DH];       // 256 B
    __shared__ float  s_slice[128];   // 512 B: this block's row slice
    __shared__ unsigned long long s_ticket;

    const int x = blockIdx.x;
    const int t = threadIdx.x;

    // ---------------- phase 1: partial column-sum + Wv projection ----------
    {
        const int b  = x & 3;
        const int qs = x >> 2;
        const int t4    = t & 255;    // float4 slot in D
        const int strip = t >> 8;     // 0..3
        const float4* vb = reinterpret_cast<const float4*>(v + (size_t)b * SQ * D);
        const int q0 = qs * 32 + strip * 8;

        float4 acc = make_float4(0.f, 0.f, 0.f, 0.f);
#pragma unroll
        for (int r = 0; r < 8; ++r) {
            float4 xv = vb[(size_t)(q0 + r) * (D / 4) + t4];
            acc.x += xv.x; acc.y += xv.y; acc.z += xv.z; acc.w += xv.w;
        }
        sred[strip * 256 + t4] = acc;
        __syncthreads();
        if (strip == 0) {
            float4 a0 = sred[t4], a1 = sred[256 + t4], a2 = sred[512 + t4], a3 = sred[768 + t4];
            float4 s;
            s.x = (a0.x + a1.x) + (a2.x + a3.x);
            s.y = (a0.y + a1.y) + (a2.y + a3.y);
            s.z = (a0.z + a1.z) + (a2.z + a3.z);
            s.w = (a0.w + a1.w) + (a2.w + a3.w);
            reinterpret_cast<float4*>(s_v)[t4] = s;
        }
        __syncthreads();

        // project: svp2[x][j] = <s_v, Wv[j,:]> ; 32 warps x 2 j's each
        const int warp = t >> 5, lane = t & 31;
        const float4* sv4 = reinterpret_cast<const float4*>(s_v);
#pragma unroll
        for (int jj = 0; jj < 2; ++jj) {
            const int j = warp * 2 + jj;
            const float4* wr = reinterpret_cast<const float4*>(Wv + (size_t)j * D);
            float s = 0.f;
#pragma unroll
            for (int i = 0; i < 8; ++i) {
                float4 w = __ldg(&wr[lane + i * 32]);
                float4 a = sv4[lane + i * 32];
                s += a.x * w.x + a.y * w.y + a.z * w.z + a.w * w.w;
            }
#pragma unroll
            for (int o = 16; o > 0; o >>= 1) s += __shfl_xor_sync(0xFFFFFFFFu, s, o);
            if (lane == 0) g_svp2[x * DH + j] = s;
        }
    }

    // ---------------- single grid sync (replay-safe tickets) ----------------
    __syncthreads();
    if (t == 0) {
        __threadfence();                                  // release svp2 writes
        s_ticket = atomicAdd(&g_tick, 1ULL);
    }
    __syncthreads();
    const unsigned long long target = (s_ticket / NB + 1ULL) * NB;
    if (t == 0) {
        while (ld_acq(&g_tick) < target) __nanosleep(64);
    }
    __syncthreads();                                      // acquire for all threads

    // ---------------- phase 2: block-local slice compute + stores ----------
    const int s  = x & 31;            // slice id: tile floats [s*128, s*128+128)
    const int b  = s >> 3;            // batch of this slice
    const int g  = x >> 5;            // tile group: tiles [g*256, g*256+256)

    // sv[b][j] for j = t < 64 (fixed-order sum over the 32 contributing blocks)
    if (t < DH) {
        float sum = (float)SQ * __ldg(&bv[t]);
#pragma unroll
        for (int qs = 0; qs < QS; ++qs)
            sum += ldcg1(&g_svp2[(qs * B + b) * DH + t]);
        s_sv[t] = sum;
    }
    __syncthreads();

    // row slice: d = (s&7)*128 + t for t < 128
    if (t < 128) {
        const int d = (s & 7) * 128 + t;
        const float4* wb = reinterpret_cast<const float4*>(Wb + (size_t)d * DH);
        float acc = 0.f;
#pragma unroll
        for (int j4 = 0; j4 < DH / 4; ++j4) {
            float4 w = __ldg(&wb[j4]);
            acc += s_sv[j4 * 4 + 0] * w.x + s_sv[j4 * 4 + 1] * w.y
                 + s_sv[j4 * 4 + 2] * w.z + s_sv[j4 * 4 + 3] * w.w;
        }
        s_slice[t] = acc * (1.0f / (float)H) + __ldg(&bb[d]);
    }
    __syncthreads();

    // stores: 32 warps x 8 tiles each; per-tile a 512B-contiguous warp store.
    {
        const int warp = t >> 5, lane = t & 31;
        const float4 val = reinterpret_cast<const float4*>(s_slice)[lane];
        const int tile0 = g * 256 + warp * 8;
        float4* obase = out4 + (size_t)tile0 * ROW_F4 + s * 32 + lane;
#pragma unroll
        for (int r = 0; r < 8; ++r)
            obase[r * ROW_F4] = val;
    }
}

extern "C" void kernel_launch(void* const* d_in, const int* in_sizes, int n_in,
                              void* d_out, int out_size) {
    // Inputs: 0=q 1=k 2=h 3=w 4=v 5=Wq 6=bq 7=Wk 8=bk 9=Wv 10=bv 11=Wb 12=bb
    const float* v  = (const float*)d_in[4];
    const float* Wv = (const float*)d_in[9];
    const float* bv = (const float*)d_in[10];
    const float* Wb = (const float*)d_in[11];
    const float* bb = (const float*)d_in[12];

    fused_kernel<<<NB, 1024>>>(v, Wv, bv, Wb, bb, (float4*)d_out);
}

// round 11
// speedup vs baseline: 1.2685x; 1.1034x over previous
#include <cuda_runtime.h>
#include <cstdint>

// Math after collapse (verified, rel_err ~9e-7):
//   attn == 1/H exactly (softmax over an exactly-broadcast head axis)
//   sv[b,j]  = <sum_q v[b,q,:], Wv[j,:]> + Sq*bv[j]
//   row[b,d] = (1/H) * <sv[b,:], Wb[d,:]> + bb[d]
//   out[s,b,d] = row[b,d]  for all s
// D-sliced phase 1: block x owns (b = x&3, d-slice [c*32, c*32+32), c = x>>2).
// It column-sums its slice over ALL q, then projects against the 8 KB Wv
// slice Wv[:, d-slice]:  svp2[x][j] = <vsum_slice, Wv[j, slice]>.
// sv[b,j] = sum over the 32 slice-blocks of b  (+ Sq*bv[j]).
static constexpr int B  = 4;
static constexpr int SQ = 1024;
static constexpr int SK = 1024;
static constexpr int D  = 1024;
static constexpr int DH = 64;
static constexpr int H  = 16;

static constexpr int NC = 32;             // d-chunks of 32 floats
static constexpr int NB = B * NC;         // 128 blocks — single co-resident wave

static constexpr int ROW_F4 = B * D / 4;  // 1024 float4 per output tile (16 KB)
// Output slice decomposition: 32 slices x 128 floats; block x owns slice
// s = x & 31 and tile-group g = x >> 5 (256 tiles each).

// Scratch (__device__ globals; no allocation allowed)
__device__ float g_svp2[NB * DH];         // 32 KB: per-block projected partials
__device__ unsigned long long g_tick;     // monotonic ticket counter (never reset)

__device__ __forceinline__ float ldcg1(const float* p) {
    float r;
    asm volatile("ld.global.cg.f32 %0, [%1];" : "=f"(r) : "l"(p));
    return r;
}
__device__ __forceinline__ unsigned long long ld_acq(const unsigned long long* p) {
    unsigned long long v;
    asm volatile("ld.global.acquire.gpu.u64 %0, [%1];" : "=l"(v) : "l"(p));
    return v;
}

// ---------------------------------------------------------------------------
// One persistent kernel, 128 blocks x 1024 threads (co-resident wave).
//  phase 1: D-sliced v column-sum (full q range) + tiny Wv-slice projection
//           -> g_svp2[x][64]
//  single replay-safe grid sync (monotonic ticket counter)
//  phase 2: block-local: sv[b] from svp2; 128-float row slice via Wb slice;
//           store slice into this block's 256 output tiles.
// ---------------------------------------------------------------------------
__global__ void __launch_bounds__(1024)
fused_kernel(const float* __restrict__ v,
             const float* __restrict__ Wv, const float* __restrict__ bv,
             const float* __restrict__ Wb, const float* __restrict__ bb,
             float4* __restrict__ out4) {
    __shared__ float4 sred[1024];     // 16 KB: stage-0 partials
    __shared__ float4 sred2[256];     // 4 KB: stage-1 partials
    __shared__ float  s_v[32];        // this block's complete vsum slice
    __shared__ float  s_sv[DH];       // 256 B
    __shared__ float  s_slice[128];   // 512 B: this block's row slice
    __shared__ unsigned long long s_ticket;

    const int x = blockIdx.x;
    const int t = threadIdx.x;
    const int b  = x & 3;
    const int c1 = x >> 2;            // d-chunk (32 floats), d0 = c1*32

    // ---------------- phase 1: D-sliced column-sum over all q --------------
    {
        const int sl = t & 7;         // float4 slot in the 32-float slice
        const int qg = t >> 3;        // 0..127 q-group
        const float* vb = v + (size_t)b * SQ * D + c1 * 32 + sl * 4;

        float4 acc = make_float4(0.f, 0.f, 0.f, 0.f);
#pragma unroll
        for (int r = 0; r < 8; ++r) {
            const float4 xv = *reinterpret_cast<const float4*>(vb + (size_t)(qg + r * 128) * D);
            acc.x += xv.x; acc.y += xv.y; acc.z += xv.z; acc.w += xv.w;
        }
        sred[t] = acc;                // [qg][sl]
        __syncthreads();

        // stage 1: 256 threads fold 128 q-groups -> 32 groups
        if (t < 256) {
            const int s2 = t & 7, g2 = t >> 3;    // g2 in 0..31
            float4 s = make_float4(0.f, 0.f, 0.f, 0.f);
#pragma unroll
            for (int i = 0; i < 4; ++i) {
                float4 a = sred[(g2 * 4 + i) * 8 + s2];
                s.x += a.x; s.y += a.y; s.z += a.z; s.w += a.w;
            }
            sred2[g2 * 8 + s2] = s;
        }
        __syncthreads();

        // stage 2: 8 threads finish (fixed order), write vsum slice
        if (t < 8) {
            float4 s = make_float4(0.f, 0.f, 0.f, 0.f);
#pragma unroll
            for (int g2 = 0; g2 < 32; ++g2) {
                float4 a = sred2[g2 * 8 + t];
                s.x += a.x; s.y += a.y; s.z += a.z; s.w += a.w;
            }
            reinterpret_cast<float4*>(s_v)[t] = s;
        }
        __syncthreads();

        // projection: svp2[x][j] = <s_v, Wv[j, d0:d0+32]>
        // 32 warps x 2 j's each; lane l covers slice element l (l<32).
        const int warp = t >> 5, lane = t & 31;
        const float a = s_v[lane];
#pragma unroll
        for (int jj = 0; jj < 2; ++jj) {
            const int j = warp * 2 + jj;
            float s = a * __ldg(&Wv[(size_t)j * D + c1 * 32 + lane]);
#pragma unroll
            for (int o = 16; o > 0; o >>= 1) s += __shfl_xor_sync(0xFFFFFFFFu, s, o);
            if (lane == 0) g_svp2[(c1 * B + b) * DH + j] = s;
        }
    }

    // ---------------- single grid sync (replay-safe tickets) ----------------
    __syncthreads();
    if (t == 0) {
        __threadfence();                                  // release svp2 writes
        s_ticket = atomicAdd(&g_tick, 1ULL);
    }
    __syncthreads();
    const unsigned long long target = (s_ticket / NB + 1ULL) * NB;
    if (t == 0) {
        while (ld_acq(&g_tick) < target) __nanosleep(32);
    }
    __syncthreads();                                      // acquire for all threads

    // ---------------- phase 2: block-local slice compute + stores ----------
    const int s  = x & 31;            // output slice: tile floats [s*128, +128)
    const int sb = s >> 3;            // batch of this slice
    const int g  = x >> 5;            // tile group: tiles [g*256, g*256+256)

    // sv[sb][j] for j = t < 64 (fixed-order sum over the 32 chunk blocks)
    if (t < DH) {
        float sum = (float)SQ * __ldg(&bv[t]);
#pragma unroll
        for (int cc = 0; cc < NC; ++cc)
            sum += ldcg1(&g_svp2[(cc * B + sb) * DH + t]);
        s_sv[t] = sum;
    }
    __syncthreads();

    // row slice: d = (s&7)*128 + t for t < 128
    if (t < 128) {
        const int d = (s & 7) * 128 + t;
        const float4* wb = reinterpret_cast<const float4*>(Wb + (size_t)d * DH);
        float acc = 0.f;
#pragma unroll
        for (int j4 = 0; j4 < DH / 4; ++j4) {
            float4 w = __ldg(&wb[j4]);
            acc += s_sv[j4 * 4 + 0] * w.x + s_sv[j4 * 4 + 1] * w.y
                 + s_sv[j4 * 4 + 2] * w.z + s_sv[j4 * 4 + 3] * w.w;
        }
        s_slice[t] = acc * (1.0f / (float)H) + __ldg(&bb[d]);
    }
    __syncthreads();

    // stores: 32 warps x 8 tiles each; per-tile a 512B-contiguous warp store.
    {
        const int warp = t >> 5, lane = t & 31;
        const float4 val = reinterpret_cast<const float4*>(s_slice)[lane];
        const int tile0 = g * 256 + warp * 8;
        float4* obase = out4 + (size_t)tile0 * ROW_F4 + s * 32 + lane;
#pragma unroll
        for (int r = 0; r < 8; ++r)
            obase[r * ROW_F4] = val;
    }
}

extern "C" void kernel_launch(void* const* d_in, const int* in_sizes, int n_in,
                              void* d_out, int out_size) {
    // Inputs: 0=q 1=k 2=h 3=w 4=v 5=Wq 6=bq 7=Wk 8=bk 9=Wv 10=bv 11=Wb 12=bb
    const float* v  = (const float*)d_in[4];
    const float* Wv = (const float*)d_in[9];
    const float* bv = (const float*)d_in[10];
    const float* Wb = (const float*)d_in[11];
    const float* bb = (const float*)d_in[12];

    fused_kernel<<<NB, 1024>>>(v, Wv, bv, Wb, bb, (float4*)d_out);
}